// round 2
// baseline (speedup 1.0000x reference)
#include <cuda_runtime.h>
#include <math.h>

// NT-Xent loss: zi, zj [4096, 256] fp32 -> scalar loss.
// Fused: normalize -> streamed 8192x8192x256 sim GEMM with online sum(exp) -> logsumexp - label -> mean.

#define NROWS 8192
#define HALF_N 4096
#define D 256
#define TILE 128
#define KCHUNK 32
#define NCHUNKS 8          // column chunks (1024 cols each)
#define INV_T 2.0f         // 1 / temperature(0.5)

__device__ float g_zn[NROWS * D];              // normalized z, row-major
__device__ float g_partial[NCHUNKS * NROWS];   // per (col-chunk, row) partial sum(exp)
__device__ float g_slabel[NROWS];              // sim[i, label(i)]

// ---------------------------------------------------------------------------
// Kernel 1: row-normalize. One block per row, 256 threads = D.
// ---------------------------------------------------------------------------
__global__ void normalize_kernel(const float* __restrict__ zi,
                                 const float* __restrict__ zj) {
    int row = blockIdx.x;
    int t = threadIdx.x;
    const float* src = (row < HALF_N) ? (zi + (size_t)row * D)
                                      : (zj + (size_t)(row - HALF_N) * D);
    float v = src[t];
    float ss = v * v;
    #pragma unroll
    for (int o = 16; o > 0; o >>= 1) ss += __shfl_xor_sync(0xffffffffu, ss, o);
    __shared__ float warp_ss[8];
    if ((t & 31) == 0) warp_ss[t >> 5] = ss;
    __syncthreads();
    float tot = 0.f;
    #pragma unroll
    for (int i = 0; i < 8; i++) tot += warp_ss[i];
    float inv = 1.0f / fmaxf(sqrtf(tot), 1e-8f);
    g_zn[(size_t)row * D + t] = v * inv;
}

// ---------------------------------------------------------------------------
// Kernel 2: fused sim-GEMM + online sum(exp) + label capture.
// Grid: (NCHUNKS, NROWS/TILE). Block: 256 threads (16x16), 8x8 per thread.
// Block (bx, by): rows [by*128, +128), cols [bx*1024, +1024).
// ---------------------------------------------------------------------------
__global__ __launch_bounds__(256, 2) void simloss_kernel() {
    const int tid = threadIdx.x;
    const int tx = tid & 15;
    const int ty = tid >> 4;
    const int rbase = blockIdx.y * TILE;
    const int cchunk = blockIdx.x;

    __shared__ float As[TILE][KCHUNK + 1];   // [row][k], pad to kill bank conflicts
    __shared__ float Bs[TILE][KCHUNK + 1];

    float accsum[8];   // running sum(exp(sim)) for this thread's 8 rows (cols it owns)
    float slab[8];     // captured label sim (0 elsewhere; exactly one thread captures)
    #pragma unroll
    for (int i = 0; i < 8; i++) { accsum[i] = 0.f; slab[i] = 0.f; }

    for (int ct = 0; ct < 8; ct++) {
        const int cbase = cchunk * (NCHUNKS * TILE) + ct * TILE;

        float acc[8][8];
        #pragma unroll
        for (int i = 0; i < 8; i++)
            #pragma unroll
            for (int j = 0; j < 8; j++) acc[i][j] = 0.f;

        for (int k0 = 0; k0 < D; k0 += KCHUNK) {
            __syncthreads();   // previous chunk's compute done
            // Each thread loads 4 float4 of A and B (128x32 each)
            #pragma unroll
            for (int q = 0; q < 4; q++) {
                int idx = tid + 256 * q;        // 0..1023
                int r   = idx >> 3;             // row in tile
                int c4  = (idx & 7) << 2;       // col*4 in chunk
                float4 va = *(const float4*)&g_zn[(size_t)(rbase + r) * D + k0 + c4];
                As[r][c4 + 0] = va.x; As[r][c4 + 1] = va.y;
                As[r][c4 + 2] = va.z; As[r][c4 + 3] = va.w;
                float4 vb = *(const float4*)&g_zn[(size_t)(cbase + r) * D + k0 + c4];
                Bs[r][c4 + 0] = vb.x; Bs[r][c4 + 1] = vb.y;
                Bs[r][c4 + 2] = vb.z; Bs[r][c4 + 3] = vb.w;
            }
            __syncthreads();

            #pragma unroll 4
            for (int kk = 0; kk < KCHUNK; kk++) {
                float a[8], b[8];
                #pragma unroll
                for (int i = 0; i < 8; i++) a[i] = As[ty + 16 * i][kk];
                #pragma unroll
                for (int j = 0; j < 8; j++) b[j] = Bs[tx + 16 * j][kk];
                #pragma unroll
                for (int i = 0; i < 8; i++)
                    #pragma unroll
                    for (int j = 0; j < 8; j++)
                        acc[i][j] = fmaf(a[i], b[j], acc[i][j]);
            }
        }

        // Epilogue for this 128x128 tile: scale, mask diagonal, accumulate exp,
        // capture label entry (col == row ^ 4096).
        #pragma unroll
        for (int i = 0; i < 8; i++) {
            int row = rbase + ty + 16 * i;
            #pragma unroll
            for (int j = 0; j < 8; j++) {
                int col = cbase + tx + 16 * j;
                float s = INV_T * acc[i][j];
                if (row != col) accsum[i] += __expf(s);
                if ((row ^ col) == HALF_N) slab[i] = s;
            }
        }
    }

    // Reduce across the 16 lanes owning each row (same ty -> same half-warp).
    #pragma unroll
    for (int i = 0; i < 8; i++) {
        #pragma unroll
        for (int o = 8; o > 0; o >>= 1) {
            accsum[i] += __shfl_xor_sync(0xffffffffu, accsum[i], o);
            slab[i]   += __shfl_xor_sync(0xffffffffu, slab[i], o);
        }
    }
    const bool haslab = ((unsigned)(rbase ^ HALF_N) >> 10) == (unsigned)cchunk;
    if (tx == 0) {
        #pragma unroll
        for (int i = 0; i < 8; i++) {
            int row = rbase + ty + 16 * i;
            g_partial[cchunk * NROWS + row] = accsum[i];
            if (haslab) g_slabel[row] = slab[i];
        }
    }
}

// ---------------------------------------------------------------------------
// Kernel 3: deterministic final reduction -> d_out[0].
// ---------------------------------------------------------------------------
__global__ void finalize_kernel(float* __restrict__ out) {
    int tid = threadIdx.x;   // 256
    float local = 0.f;
    for (int row = tid; row < NROWS; row += 256) {
        float s = 0.f;
        #pragma unroll
        for (int c = 0; c < NCHUNKS; c++) s += g_partial[c * NROWS + row];
        local += logf(s) - g_slabel[row];
    }
    #pragma unroll
    for (int o = 16; o > 0; o >>= 1) local += __shfl_xor_sync(0xffffffffu, local, o);
    __shared__ float ws[8];
    if ((tid & 31) == 0) ws[tid >> 5] = local;
    __syncthreads();
    if (tid == 0) {
        float tot = 0.f;
        #pragma unroll
        for (int i = 0; i < 8; i++) tot += ws[i];
        out[0] = tot / (float)NROWS;
    }
}

extern "C" void kernel_launch(void* const* d_in, const int* in_sizes, int n_in,
                              void* d_out, int out_size) {
    const float* zi = (const float*)d_in[0];
    const float* zj = (const float*)d_in[1];
    float* out = (float*)d_out;

    normalize_kernel<<<NROWS, 256>>>(zi, zj);
    dim3 grid(NCHUNKS, NROWS / TILE);
    simloss_kernel<<<grid, 256>>>();
    finalize_kernel<<<1, 256>>>(out);
}

// round 4
// speedup vs baseline: 7.4891x; 7.4891x over previous
#include <cuda_runtime.h>
#include <cuda_bf16.h>
#include <cstdint>
#include <math.h>

// NT-Xent loss via bf16 mma.sync (HMMA): normalize(fp32->bf16) ->
// fused simGEMM + exp-sum epilogue -> finalize.

#define NROWS 8192
#define HALF_N 4096
#define DIM 256
#define TILE 128
#define NCOLCHUNK 2
#define COLS_PER_CHUNK 4096
#define NTILES 32           // 128-col tiles per chunk
#define ROWB 512            // bytes per smem tile row (256 bf16)

__device__ __nv_bfloat16 g_zbf[NROWS * DIM];
__device__ float g_partial[NROWS * 4];
__device__ float g_slabel[NROWS];

__device__ __forceinline__ uint32_t smem_u32(const void* p) {
    uint32_t a;
    asm("{ .reg .u64 t; cvta.to.shared.u64 t, %1; cvt.u32.u64 %0, t; }" : "=r"(a) : "l"(p));
    return a;
}

#define CP16(dst, src) asm volatile("cp.async.cg.shared.global [%0], [%1], 16;" :: "r"(dst), "l"(src) : "memory")
#define CP_COMMIT()    asm volatile("cp.async.commit_group;" ::: "memory")
#define CP_WAIT1()     asm volatile("cp.async.wait_group 1;" ::: "memory")

__device__ __forceinline__ void ldm_x4(uint32_t* r, uint32_t addr) {
    asm volatile("ldmatrix.sync.aligned.m8n8.x4.shared.b16 {%0,%1,%2,%3}, [%4];"
                 : "=r"(r[0]), "=r"(r[1]), "=r"(r[2]), "=r"(r[3]) : "r"(addr));
}
__device__ __forceinline__ void mma16816(float* c, const uint32_t* a, uint32_t b0, uint32_t b1) {
    asm volatile("mma.sync.aligned.m16n8k16.row.col.f32.bf16.bf16.f32 "
                 "{%0,%1,%2,%3}, {%4,%5,%6,%7}, {%8,%9}, {%0,%1,%2,%3};"
                 : "+f"(c[0]), "+f"(c[1]), "+f"(c[2]), "+f"(c[3])
                 : "r"(a[0]), "r"(a[1]), "r"(a[2]), "r"(a[3]), "r"(b0), "r"(b1));
}

// Load one 128x256 bf16 tile (64KB) into smem with 16B XOR swizzle.
// 256 threads x 16 cp.async of 16B.
__device__ __forceinline__ void load_tile(uint32_t dst, int rowbase, int tid) {
    const char* base = (const char*)g_zbf + (size_t)rowbase * ROWB;
    #pragma unroll
    for (int i = 0; i < 16; i++) {
        int idx = tid + 256 * i;     // 0..4095
        int r = idx >> 5;            // tile row (0..127)
        int c = idx & 31;            // 16B chunk (0..31)
        uint32_t d = dst + r * ROWB + ((c ^ (r & 7)) << 4);
        CP16(d, base + (size_t)r * ROWB + c * 16);
    }
}

// ---------------- Kernel 1: normalize fp32 -> bf16, warp per row ----------------
__global__ void normalize_kernel(const float* __restrict__ zi,
                                 const float* __restrict__ zj) {
    int wid = threadIdx.x >> 5, lane = threadIdx.x & 31;
    int row = blockIdx.x * 8 + wid;
    const float* src = (row < HALF_N) ? (zi + (size_t)row * DIM)
                                      : (zj + (size_t)(row - HALF_N) * DIM);
    const float4* s4 = (const float4*)src;
    float4 a = s4[lane * 2];
    float4 b = s4[lane * 2 + 1];
    float ss = a.x*a.x + a.y*a.y + a.z*a.z + a.w*a.w
             + b.x*b.x + b.y*b.y + b.z*b.z + b.w*b.w;
    #pragma unroll
    for (int o = 16; o > 0; o >>= 1) ss += __shfl_xor_sync(0xffffffffu, ss, o);
    float inv = rsqrtf(fmaxf(ss, 1e-16f));
    __nv_bfloat162 p0 = __float22bfloat162_rn(make_float2(a.x * inv, a.y * inv));
    __nv_bfloat162 p1 = __float22bfloat162_rn(make_float2(a.z * inv, a.w * inv));
    __nv_bfloat162 p2 = __float22bfloat162_rn(make_float2(b.x * inv, b.y * inv));
    __nv_bfloat162 p3 = __float22bfloat162_rn(make_float2(b.z * inv, b.w * inv));
    uint4 out;
    out.x = *(uint32_t*)&p0; out.y = *(uint32_t*)&p1;
    out.z = *(uint32_t*)&p2; out.w = *(uint32_t*)&p3;
    *(uint4*)(&g_zbf[(size_t)row * DIM + lane * 8]) = out;
}

// ---------------- Kernel 2: fused sim GEMM (mma.sync bf16) + exp-sum ------------
// Grid (2, 64). 256 threads = 8 warps: warp_m = wid&3 (32 rows each),
// warp_n = wid>>2 (64 cols each). Warp tile 32x64, frag m16n8k16.
// Smem: A (64KB, full K=256) + B double buffer (2 x 64KB) = 192KB dynamic.
__global__ __launch_bounds__(256, 1) void simloss_kernel() {
    extern __shared__ char smem[];
    const uint32_t sb = smem_u32(smem);
    const uint32_t A_OFF = sb;
    const uint32_t B_OFF[2] = { sb + 65536, sb + 131072 };

    const int tid = threadIdx.x, wid = tid >> 5, lane = tid & 31;
    const int wm = wid & 3, wn = wid >> 2;
    const int cc = blockIdx.x;
    const int rbase = blockIdx.y * TILE;

    // Preload A and first two B tiles.
    load_tile(A_OFF, rbase, tid);
    load_tile(B_OFF[0], cc * COLS_PER_CHUNK, tid);
    CP_COMMIT();                                    // group: {A, B0}
    load_tile(B_OFF[1], cc * COLS_PER_CHUNK + TILE, tid);
    CP_COMMIT();                                    // group: {B1}

    // ldmatrix per-lane row bases (constant over k-steps).
    const int h = lane >> 4;                        // 16B-half select
    uint32_t a_row[2], a_x[2];
    #pragma unroll
    for (int m = 0; m < 2; m++) {
        int r = wm * 32 + m * 16 + (lane & 15);
        a_row[m] = A_OFF + r * ROWB;
        a_x[m] = r & 7;
    }
    uint32_t b_row[4], b_x[4];
    #pragma unroll
    for (int n = 0; n < 4; n++) {
        int r = wn * 64 + n * 16 + (lane & 15);
        b_row[n] = r * ROWB;
        b_x[n] = r & 7;
    }

    // Per-thread global rows for the 4 accum row positions [m][rhalf].
    int growr[2][2];
    #pragma unroll
    for (int m = 0; m < 2; m++)
        #pragma unroll
        for (int rh = 0; rh < 2; rh++)
            growr[m][rh] = rbase + wm * 32 + m * 16 + (lane >> 2) + rh * 8;

    float sum[2][2] = {{0.f, 0.f}, {0.f, 0.f}};
    float slab[2][2] = {{0.f, 0.f}, {0.f, 0.f}};

    for (int t = 0; t < NTILES; t++) {
        const uint32_t bb = B_OFF[t & 1];
        CP_WAIT1();                 // tile t resident (t+1 still in flight)
        __syncthreads();

        float acc[2][8][4];
        #pragma unroll
        for (int m = 0; m < 2; m++)
            #pragma unroll
            for (int n = 0; n < 8; n++)
                #pragma unroll
                for (int k = 0; k < 4; k++) acc[m][n][k] = 0.f;

        #pragma unroll
        for (int ks = 0; ks < 16; ks++) {
            const uint32_t c = 2 * ks + h;
            uint32_t ar[2][4], br[4][4];
            #pragma unroll
            for (int m = 0; m < 2; m++)
                ldm_x4(ar[m], a_row[m] + ((c ^ a_x[m]) << 4));
            #pragma unroll
            for (int n = 0; n < 4; n++)
                ldm_x4(br[n], bb + b_row[n] + ((c ^ b_x[n]) << 4));
            #pragma unroll
            for (int m = 0; m < 2; m++)
                #pragma unroll
                for (int n = 0; n < 4; n++) {
                    mma16816(acc[m][2 * n],     ar[m], br[n][0], br[n][2]);
                    mma16816(acc[m][2 * n + 1], ar[m], br[n][1], br[n][3]);
                }
        }

        __syncthreads();            // everyone done reading B[t&1]
        if (t + 2 < NTILES) {
            load_tile(B_OFF[t & 1], cc * COLS_PER_CHUNK + (t + 2) * TILE, tid);
        }
        CP_COMMIT();                // keep group count uniform

        // Epilogue on registers (overlaps in-flight cp.async).
        const int cbase = cc * COLS_PER_CHUNK + t * TILE + wn * 64 + (lane & 3) * 2;
        #pragma unroll
        for (int m = 0; m < 2; m++)
            #pragma unroll
            for (int n = 0; n < 8; n++)
                #pragma unroll
                for (int k = 0; k < 4; k++) {
                    const int rh = k >> 1;
                    const int grow = growr[m][rh];
                    const int gcol = cbase + n * 8 + (k & 1);
                    float s = 2.0f * acc[m][n][k];      // / temperature
                    float e = __expf(s);
                    if (gcol != grow) sum[m][rh] += e;  // mask diagonal
                    if (gcol == (grow ^ HALF_N)) slab[m][rh] = s;
                }
    }

    // Reduce across the 4 lanes sharing each row (lane&3 varies).
    #pragma unroll
    for (int m = 0; m < 2; m++)
        #pragma unroll
        for (int rh = 0; rh < 2; rh++) {
            #pragma unroll
            for (int o = 1; o < 4; o <<= 1) {
                sum[m][rh]  += __shfl_xor_sync(0xffffffffu, sum[m][rh], o);
                slab[m][rh] += __shfl_xor_sync(0xffffffffu, slab[m][rh], o);
            }
        }
    if ((lane & 3) == 0) {
        #pragma unroll
        for (int m = 0; m < 2; m++)
            #pragma unroll
            for (int rh = 0; rh < 2; rh++) {
                const int grow = growr[m][rh];
                g_partial[grow * 4 + cc * 2 + wn] = sum[m][rh];
                const int lb = grow ^ HALF_N;   // label column
                if ((lb >> 12) == cc && (((lb >> 6) & 1) == wn))
                    g_slabel[grow] = slab[m][rh];
            }
    }
}

// ---------------- Kernel 3: deterministic final reduction ----------------
__global__ void finalize_kernel(float* __restrict__ out) {
    int tid = threadIdx.x;   // 256
    float local = 0.f;
    for (int row = tid; row < NROWS; row += 256) {
        float s = g_partial[row * 4 + 0] + g_partial[row * 4 + 1]
                + g_partial[row * 4 + 2] + g_partial[row * 4 + 3];
        local += logf(s) - g_slabel[row];
    }
    #pragma unroll
    for (int o = 16; o > 0; o >>= 1) local += __shfl_xor_sync(0xffffffffu, local, o);
    __shared__ float ws[8];
    if ((tid & 31) == 0) ws[tid >> 5] = local;
    __syncthreads();
    if (tid == 0) {
        float tot = 0.f;
        #pragma unroll
        for (int i = 0; i < 8; i++) tot += ws[i];
        out[0] = tot / (float)NROWS;
    }
}

extern "C" void kernel_launch(void* const* d_in, const int* in_sizes, int n_in,
                              void* d_out, int out_size) {
    const float* zi = (const float*)d_in[0];
    const float* zj = (const float*)d_in[1];
    float* out = (float*)d_out;

    cudaFuncSetAttribute(simloss_kernel,
                         cudaFuncAttributeMaxDynamicSharedMemorySize, 196608);

    normalize_kernel<<<NROWS / 8, 256>>>(zi, zj);
    dim3 grid(NCOLCHUNK, NROWS / TILE);
    simloss_kernel<<<grid, 256, 196608>>>();
    finalize_kernel<<<1, 256>>>(out);
}